// round 5
// baseline (speedup 1.0000x reference)
#include <cuda_runtime.h>
#include <math_constants.h>

// CrossEntropyLoss: mean over rows of  sum_c -log_softmax(pred)[n,c] * target[n,c]
//   = mean_n [ lse_n * (sum_c t) - sum_c t*x ],  lse_n = max_n + log(sum exp(x - max_n))
// Single fused pass, single kernel: each input element read exactly once (~2.1 GB),
// final mean via last-CTA-done reduction (no second launch).

#define N_ROWS   8192
#define C_COLS   32000
#define C_VEC    (C_COLS / 4)   // 8000 float4 per row per tensor
#define THREADS  256
#define NWARPS   (THREADS / 32)

// Global accumulator + completion counter (no cudaMalloc allowed anywhere).
// Both are left at 0 by the last CTA so the kernel is graph-replay-safe.
__device__ float        g_sum   = 0.0f;
__device__ unsigned int g_count = 0u;

__global__ void __launch_bounds__(THREADS)
ce_fused_kernel(const float* __restrict__ pred, const float* __restrict__ tgt,
                float* __restrict__ out)
{
    const int row = blockIdx.x;
    const float4* __restrict__ p = reinterpret_cast<const float4*>(pred + (size_t)row * C_COLS);
    const float4* __restrict__ t = reinterpret_cast<const float4*>(tgt  + (size_t)row * C_COLS);
    const int tid = threadIdx.x;

    // Online logsumexp state + linear accumulators
    float m    = -CUDART_INF_F;  // running max
    float s    = 0.0f;           // sum exp(x - m)
    float dacc = 0.0f;           // sum t*x
    float tacc = 0.0f;           // sum t

    // 8000 vec4 / 256 threads = 31.25 iters/thread. Unroll 4 -> up to 8
    // front-batched LDG.128 per group (MLP depth). __ldcs: streaming
    // evict-first, data is single-use.
    #pragma unroll 4
    for (int i = tid; i < C_VEC; i += THREADS) {
        float4 x = __ldcs(&p[i]);
        float4 y = __ldcs(&t[i]);

        dacc = fmaf(x.x, y.x, dacc);
        dacc = fmaf(x.y, y.y, dacc);
        dacc = fmaf(x.z, y.z, dacc);
        dacc = fmaf(x.w, y.w, dacc);
        tacc += (y.x + y.y) + (y.z + y.w);

        // local max of the 4; rescale only when it beats the running max
        // (short predicated arm, ~1 exp per element total)
        float lm = fmaxf(fmaxf(x.x, x.y), fmaxf(x.z, x.w));
        if (lm > m) {
            s *= __expf(m - lm);   // first hit: s==0, __expf(-inf)=0 -> stays 0
            m = lm;
        }
        s += __expf(x.x - m) + __expf(x.y - m)
           + __expf(x.z - m) + __expf(x.w - m);
    }

    // ---- warp reduction of (m, s, dacc, tacc) ----
    #pragma unroll
    for (int off = 16; off > 0; off >>= 1) {
        float m2 = __shfl_xor_sync(0xFFFFFFFFu, m, off);
        float s2 = __shfl_xor_sync(0xFFFFFFFFu, s, off);
        float nm = fmaxf(m, m2);
        s = s * __expf(m - nm) + s2 * __expf(m2 - nm);
        m = nm;
        dacc += __shfl_xor_sync(0xFFFFFFFFu, dacc, off);
        tacc += __shfl_xor_sync(0xFFFFFFFFu, tacc, off);
    }

    // ---- block reduction across warps ----
    __shared__ float sh_m[NWARPS], sh_s[NWARPS], sh_d[NWARPS], sh_t[NWARPS];
    const int wid = tid >> 5;
    const int lid = tid & 31;
    if (lid == 0) {
        sh_m[wid] = m; sh_s[wid] = s; sh_d[wid] = dacc; sh_t[wid] = tacc;
    }
    __syncthreads();

    if (tid == 0) {
        float M = sh_m[0], S = sh_s[0], D = sh_d[0], T = sh_t[0];
        #pragma unroll
        for (int w = 1; w < NWARPS; w++) {
            float m2 = sh_m[w], s2 = sh_s[w];
            float nm = fmaxf(M, m2);
            S = S * __expf(M - nm) + s2 * __expf(m2 - nm);
            M = nm;
            D += sh_d[w];
            T += sh_t[w];
        }
        float lse = M + __logf(S);
        float row_ce = lse * T - D;

        // accumulate scaled row loss; last CTA finalizes + resets state
        atomicAdd(&g_sum, row_ce * (1.0f / (float)N_ROWS));
        __threadfence();
        unsigned int ticket = atomicAdd(&g_count, 1u);
        if (ticket == (unsigned int)(N_ROWS - 1)) {
            out[0]  = g_sum;
            g_sum   = 0.0f;   // reset for next graph replay
            g_count = 0u;
        }
    }
}

extern "C" void kernel_launch(void* const* d_in, const int* in_sizes, int n_in,
                              void* d_out, int out_size)
{
    const float* pred = (const float*)d_in[0];
    const float* tgt  = (const float*)d_in[1];
    float* out = (float*)d_out;

    ce_fused_kernel<<<N_ROWS, THREADS>>>(pred, tgt, out);
}